// round 11
// baseline (speedup 1.0000x reference)
#include <cuda_runtime.h>

#define D 64
#define GMAX 64
#define NMAX 100000
#define EMAX 1250000

// ---- scratch (device globals). float4 => 16B alignment. ----
__device__ float4 g_h4[NMAX * D / 4];     // h' = (x @ W) * dis[row]
__device__ float4 g_buf04[NMAX * D / 4];  // layer ping-pong
__device__ float4 g_buf14[NMAX * D / 4];
__device__ int   g_degE[NMAX];            // real in-degree (no self loop)
__device__ int   g_start[NMAX];           // CSR exclusive offsets
__device__ int   g_cursor[NMAX];          // fill cursors
__device__ int   g_csr[EMAX];             // src ids grouped by dst
__device__ int   g_bsum[256];             // scan block sums
__device__ int   g_boff[256];             // scan block offsets
__device__ float g_dis[NMAX];
__device__ float g_cnt[GMAX];
__device__ float g_gmax[GMAX * D];
__device__ float g_gsum[GMAX * D];

#define g_h ((float*)g_h4)

// ---- init ----
__global__ void k_init(float* __restrict__ out_graph, int n) {
    int i = blockIdx.x * blockDim.x + threadIdx.x;
    if (i < n) g_degE[i] = 0;
    if (i < GMAX) g_cnt[i] = 0.0f;
    if (i < GMAX * D) { g_gmax[i] = 0.0f; g_gsum[i] = 0.0f; }
    if (i < GMAX * 2 * D) out_graph[i] = 0.0f;
}

// ---- in-degree over destinations (int) ----
__global__ void k_deg(const int* __restrict__ ei, int e) {
    int i = blockIdx.x * blockDim.x + threadIdx.x;
    if (i < e) atomicAdd(&g_degE[ei[e + i]], 1);
}

// ---- dis = rsqrt(degE + 1); per-graph node counts ----
__global__ void k_dis(const int* __restrict__ batch, int n) {
    int i = blockIdx.x * blockDim.x + threadIdx.x;
    if (i < n) {
        g_dis[i] = rsqrtf((float)(g_degE[i] + 1));
        atomicAdd(&g_cnt[batch[i]], 1.0f);
    }
}

// ---- deterministic 2-level exclusive scan of g_degE -> g_start ----
__global__ void k_scan1(int n) {
    __shared__ int s[512];
    int i = blockIdx.x * 512 + threadIdx.x;
    int v = (i < n) ? g_degE[i] : 0;
    s[threadIdx.x] = v;
    __syncthreads();
    for (int off = 1; off < 512; off <<= 1) {
        int t = (threadIdx.x >= off) ? s[threadIdx.x - off] : 0;
        __syncthreads();
        s[threadIdx.x] += t;
        __syncthreads();
    }
    if (i < n) g_start[i] = s[threadIdx.x] - v;   // exclusive
    if (threadIdx.x == 511) g_bsum[blockIdx.x] = s[511];
}
__global__ void k_scan2(int nb) {
    __shared__ int s[256];
    int v = (threadIdx.x < nb) ? g_bsum[threadIdx.x] : 0;
    s[threadIdx.x] = v;
    __syncthreads();
    for (int off = 1; off < 256; off <<= 1) {
        int t = (threadIdx.x >= off) ? s[threadIdx.x - off] : 0;
        __syncthreads();
        s[threadIdx.x] += t;
        __syncthreads();
    }
    if (threadIdx.x < nb) g_boff[threadIdx.x] = s[threadIdx.x] - v;
}
__global__ void k_scan3(int n) {
    int i = blockIdx.x * blockDim.x + threadIdx.x;
    if (i < n) {
        int st = g_start[i] + g_boff[i >> 9];
        g_start[i] = st;
        g_cursor[i] = st;
    }
}

// ---- CSR fill: group src by dst (order within node nondeterministic; sum-safe) ----
__global__ void k_fill(const int* __restrict__ ei, int e) {
    int i = blockIdx.x * blockDim.x + threadIdx.x;
    if (i >= e) return;
    int dst = ei[e + i];
    int pos = atomicAdd(&g_cursor[dst], 1);
    g_csr[pos] = ei[i];
}

// ---- h' = (x @ W) * dis[row] ----
// 128 rows/block, 128 threads. Thread (r, c) computes rows r, r+32, r+64, r+96,
// cols {4j+c}. Per k: 4 xs LDS + 16 ws LDS reused across 4 rows -> 64 FMA
// (LDS/FMA 0.31 vs 0.56). Rotation (4*row)&63 is identical for all 4 rows
// (4*32 = 128 = 0 mod 64), warp-level bank pattern unchanged from proven kernel.
__global__ void k_gemm(const float* __restrict__ x, const float* __restrict__ W, int n) {
    __shared__ float xs[128 * 64];   // 32KB, rotated rows
    __shared__ float ws[64 * 64];    // 16KB -> total 48KB = limit
    int t = threadIdx.x;             // 0..127
    int R0 = blockIdx.x * 128;
    int rows = min(128, n - R0);

    for (int i = t; i < 64 * 16; i += 128)
        ((float4*)ws)[i] = ((const float4*)W)[i];
    for (int i = t; i < rows * 16; i += 128) {
        int rr = i >> 4, c4 = i & 15;
        int roff = ((c4 * 4 + rr * 4) & 63);          // rotated, 16B-aligned
        *(float4*)(xs + rr * 64 + roff) = *((const float4*)(x + (size_t)(R0 + rr) * 64) + c4);
    }
    __syncthreads();

    int r = t >> 2;      // 0..31 -> rows r, r+32, r+64, r+96
    int c = t & 3;       // 0..3  -> cols 4j+c
    int rot = (r * 4) & 63;
    const float* x0 = xs + r * 64;
    const float* x1 = xs + (r + 32) * 64;
    const float* x2 = xs + (r + 64) * 64;
    const float* x3 = xs + (r + 96) * 64;

    float acc0[16], acc1[16], acc2[16], acc3[16];
#pragma unroll
    for (int j = 0; j < 16; j++) { acc0[j] = 0.f; acc1[j] = 0.f; acc2[j] = 0.f; acc3[j] = 0.f; }
#pragma unroll 16
    for (int k = 0; k < 64; k++) {
        int koff = (k + rot) & 63;
        float xv0 = x0[koff];
        float xv1 = x1[koff];
        float xv2 = x2[koff];
        float xv3 = x3[koff];
        const float* wrow = ws + k * 64;
#pragma unroll
        for (int j = 0; j < 16; j++) {
            float w = wrow[4 * j + c];
            acc0[j] += xv0 * w;
            acc1[j] += xv1 * w;
            acc2[j] += xv2 * w;
            acc3[j] += xv3 * w;
        }
    }
#pragma unroll
    for (int q = 0; q < 4; q++) {
        int gr = R0 + r + q * 32;
        if (r + q * 32 < rows) {
            float s = g_dis[gr];
            float* hp = g_h + (size_t)gr * 64;
            const float* a = (q == 0) ? acc0 : (q == 1) ? acc1 : (q == 2) ? acc2 : acc3;
#pragma unroll
            for (int j = 0; j < 16; j++) hp[4 * j + c] = a[j] * s;
        }
    }
}

// ---- fused gather + epilogue + pooling ----
// One warp per node (8 nodes/block of 256). Half-warps process interleaved edges
// (stride 2, 2-deep unroll = 4 loads in flight), merged via shfl_xor(16).
__global__ void k_gather(const float* __restrict__ b, const int* __restrict__ batch,
                         float* __restrict__ xout, int n) {
    int t = threadIdx.x;
    int lane = t & 31;
    int w = t >> 5;            // warp 0..7 -> node
    int ln = lane & 15;        // float4 lane (cols 4*ln .. 4*ln+3)
    int half = lane >> 4;      // 0/1: which edge parity this half-warp takes
    int node = blockIdx.x * 8 + w;

    float4 acc = {0.f, 0.f, 0.f, 0.f};
    float4 out = {0.f, 0.f, 0.f, 0.f};
    if (node < n) {
        if (half == 0) acc = g_h4[(size_t)node * 16 + ln];   // self loop (already *dis)
        int st = g_start[node];
        int end = st + g_degE[node];
        float4 acc2 = {0.f, 0.f, 0.f, 0.f};
        int k = st + half;
        for (; k + 2 < end; k += 4) {
            int s0 = g_csr[k], s1 = g_csr[k + 2];
            float4 v0 = g_h4[(size_t)s0 * 16 + ln];
            float4 v1 = g_h4[(size_t)s1 * 16 + ln];
            acc.x += v0.x; acc.y += v0.y; acc.z += v0.z; acc.w += v0.w;
            acc2.x += v1.x; acc2.y += v1.y; acc2.z += v1.z; acc2.w += v1.w;
        }
        for (; k < end; k += 2) {
            int s0 = g_csr[k];
            float4 v0 = g_h4[(size_t)s0 * 16 + ln];
            acc.x += v0.x; acc.y += v0.y; acc.z += v0.z; acc.w += v0.w;
        }
        acc.x += acc2.x; acc.y += acc2.y; acc.z += acc2.z; acc.w += acc2.w;
    }
    // merge half-warps (lane ln gets lane ln+16's partial)
    acc.x += __shfl_xor_sync(0xffffffffu, acc.x, 16);
    acc.y += __shfl_xor_sync(0xffffffffu, acc.y, 16);
    acc.z += __shfl_xor_sync(0xffffffffu, acc.z, 16);
    acc.w += __shfl_xor_sync(0xffffffffu, acc.w, 16);

    if (node < n && half == 0) {
        float d = g_dis[node];
        float4 bb = ((const float4*)b)[ln];
        out.x = fmaxf(fmaf(d, acc.x, bb.x), 0.f);
        out.y = fmaxf(fmaf(d, acc.y, bb.y), 0.f);
        out.z = fmaxf(fmaf(d, acc.z, bb.z), 0.f);
        out.w = fmaxf(fmaf(d, acc.w, bb.w), 0.f);
        ((float4*)xout)[(size_t)node * 16 + ln] = out;
    }

    // pooling over the block's 8 nodes
    int R0 = blockIdx.x * 8;
    int last = min(R0 + 7, n - 1);
    int gfirst = batch[R0];
    int glast = batch[last];

    __shared__ float4 ssum[8][16];
    __shared__ float4 smax[8][16];
    if (half == 0) { ssum[w][ln] = out; smax[w][ln] = out; }  // out==0 if node>=n: safe
    __syncthreads();

    if (gfirst == glast) {
#pragma unroll
        for (int off = 4; off > 0; off >>= 1) {
            if (w < off && half == 0) {
                float4 a = ssum[w][ln], c2 = ssum[w + off][ln];
                a.x += c2.x; a.y += c2.y; a.z += c2.z; a.w += c2.w;
                ssum[w][ln] = a;
                float4 m = smax[w][ln], c3 = smax[w + off][ln];
                m.x = fmaxf(m.x, c3.x); m.y = fmaxf(m.y, c3.y);
                m.z = fmaxf(m.z, c3.z); m.w = fmaxf(m.w, c3.w);
                smax[w][ln] = m;
            }
            __syncthreads();
        }
        if (w == 0 && half == 0) {
            float4 s = ssum[0][ln];
            float4 m = smax[0][ln];
            float* gs = &g_gsum[gfirst * 64 + ln * 4];
            unsigned int* gm = (unsigned int*)&g_gmax[gfirst * 64 + ln * 4];
            atomicAdd(gs + 0, s.x); atomicAdd(gs + 1, s.y);
            atomicAdd(gs + 2, s.z); atomicAdd(gs + 3, s.w);
            atomicMax(gm + 0, __float_as_uint(m.x));
            atomicMax(gm + 1, __float_as_uint(m.y));
            atomicMax(gm + 2, __float_as_uint(m.z));
            atomicMax(gm + 3, __float_as_uint(m.w));
        }
    } else if (node < n && half == 0) {
        int g = batch[node];
        float* gs = &g_gsum[g * 64 + ln * 4];
        unsigned int* gm = (unsigned int*)&g_gmax[g * 64 + ln * 4];
        atomicAdd(gs + 0, out.x); atomicAdd(gs + 1, out.y);
        atomicAdd(gs + 2, out.z); atomicAdd(gs + 3, out.w);
        atomicMax(gm + 0, __float_as_uint(out.x));
        atomicMax(gm + 1, __float_as_uint(out.y));
        atomicMax(gm + 2, __float_as_uint(out.z));
        atomicMax(gm + 3, __float_as_uint(out.w));
    }
}

// ---- accumulate per-layer pooled features into graph output; reset pool buffers ----
__global__ void k_graphacc(float* __restrict__ out_graph) {
    int i = blockIdx.x * blockDim.x + threadIdx.x;
    if (i >= GMAX * 64) return;
    int g = i >> 6, j = i & 63;
    out_graph[g * 128 + j] += g_gmax[i];
    out_graph[g * 128 + 64 + j] += g_gsum[i] / g_cnt[g];
    g_gmax[i] = 0.0f;
    g_gsum[i] = 0.0f;
}

extern "C" void kernel_launch(void* const* d_in, const int* in_sizes, int n_in,
                              void* d_out, int out_size) {
    const float* x = (const float*)d_in[0];
    const int* ei = (const int*)d_in[1];
    const int* batch = (const int*)d_in[2];
    const float* Ws[3] = {(const float*)d_in[3], (const float*)d_in[5], (const float*)d_in[7]};
    const float* bs[3] = {(const float*)d_in[4], (const float*)d_in[6], (const float*)d_in[8]};

    int n = in_sizes[2];
    int e = in_sizes[1] / 2;

    float* out = (float*)d_out;
    float* out_nodes = out;
    float* out_graph = out + (size_t)n * 64;

    float *buf0, *buf1;
    cudaGetSymbolAddress((void**)&buf0, g_buf04);
    cudaGetSymbolAddress((void**)&buf1, g_buf14);

    int nb = (n + 511) / 512;   // scan blocks (<=256)

    k_init<<<(n + 255) / 256, 256>>>(out_graph, n);
    k_deg<<<(e + 255) / 256, 256>>>(ei, e);
    k_dis<<<(n + 255) / 256, 256>>>(batch, n);
    k_scan1<<<nb, 512>>>(n);
    k_scan2<<<1, 256>>>(nb);
    k_scan3<<<(n + 255) / 256, 256>>>(n);
    k_fill<<<(e + 255) / 256, 256>>>(ei, e);

    const float* xin = x;
    float* xouts[3] = {buf0, buf1, out_nodes};
    for (int l = 0; l < 3; l++) {
        k_gemm<<<(n + 127) / 128, 128>>>(xin, Ws[l], n);
        k_gather<<<(n + 7) / 8, 256>>>(bs[l], batch, xouts[l], n);
        k_graphacc<<<16, 256>>>(out_graph);
        xin = xouts[l];
    }
}

// round 12
// speedup vs baseline: 1.2080x; 1.2080x over previous
#include <cuda_runtime.h>

#define D 64
#define GMAX 64
#define NMAX 100000
#define EMAX 1250000

// ---- scratch (device globals). float4 => 16B alignment. ----
__device__ float4 g_h4[NMAX * D / 4];     // h' = (x @ W) * dis[row]
__device__ float4 g_buf04[NMAX * D / 4];  // layer ping-pong
__device__ float4 g_buf14[NMAX * D / 4];
__device__ int   g_degE[NMAX];            // real in-degree (no self loop)
__device__ int   g_start[NMAX];           // CSR exclusive offsets
__device__ int   g_cursor[NMAX];          // fill cursors
__device__ int   g_csr[EMAX];             // src ids grouped by dst
__device__ int   g_bsum[256];             // scan block sums
__device__ int   g_boff[256];             // scan block offsets
__device__ float g_dis[NMAX];
__device__ float g_cnt[GMAX];
__device__ float g_gmax[GMAX * D];
__device__ float g_gsum[GMAX * D];

#define g_h ((float*)g_h4)

// ---- init ----
__global__ void k_init(float* __restrict__ out_graph, int n) {
    int i = blockIdx.x * blockDim.x + threadIdx.x;
    if (i < n) g_degE[i] = 0;
    if (i < GMAX) g_cnt[i] = 0.0f;
    if (i < GMAX * D) { g_gmax[i] = 0.0f; g_gsum[i] = 0.0f; }
    if (i < GMAX * 2 * D) out_graph[i] = 0.0f;
}

// ---- in-degree over destinations (int) ----
__global__ void k_deg(const int* __restrict__ ei, int e) {
    int i = blockIdx.x * blockDim.x + threadIdx.x;
    if (i < e) atomicAdd(&g_degE[ei[e + i]], 1);
}

// ---- dis = rsqrt(degE + 1); per-graph node counts ----
__global__ void k_dis(const int* __restrict__ batch, int n) {
    int i = blockIdx.x * blockDim.x + threadIdx.x;
    if (i < n) {
        g_dis[i] = rsqrtf((float)(g_degE[i] + 1));
        atomicAdd(&g_cnt[batch[i]], 1.0f);
    }
}

// ---- deterministic 2-level exclusive scan of g_degE -> g_start ----
__global__ void k_scan1(int n) {
    __shared__ int s[512];
    int i = blockIdx.x * 512 + threadIdx.x;
    int v = (i < n) ? g_degE[i] : 0;
    s[threadIdx.x] = v;
    __syncthreads();
    for (int off = 1; off < 512; off <<= 1) {
        int t = (threadIdx.x >= off) ? s[threadIdx.x - off] : 0;
        __syncthreads();
        s[threadIdx.x] += t;
        __syncthreads();
    }
    if (i < n) g_start[i] = s[threadIdx.x] - v;   // exclusive
    if (threadIdx.x == 511) g_bsum[blockIdx.x] = s[511];
}
__global__ void k_scan2(int nb) {
    __shared__ int s[256];
    int v = (threadIdx.x < nb) ? g_bsum[threadIdx.x] : 0;
    s[threadIdx.x] = v;
    __syncthreads();
    for (int off = 1; off < 256; off <<= 1) {
        int t = (threadIdx.x >= off) ? s[threadIdx.x - off] : 0;
        __syncthreads();
        s[threadIdx.x] += t;
        __syncthreads();
    }
    if (threadIdx.x < nb) g_boff[threadIdx.x] = s[threadIdx.x] - v;
}
__global__ void k_scan3(int n) {
    int i = blockIdx.x * blockDim.x + threadIdx.x;
    if (i < n) {
        int st = g_start[i] + g_boff[i >> 9];
        g_start[i] = st;
        g_cursor[i] = st;
    }
}

// ---- CSR fill: group src by dst (order within node nondeterministic; sum-safe) ----
__global__ void k_fill(const int* __restrict__ ei, int e) {
    int i = blockIdx.x * blockDim.x + threadIdx.x;
    if (i >= e) return;
    int dst = ei[e + i];
    int pos = atomicAdd(&g_cursor[dst], 1);
    g_csr[pos] = ei[i];
}

// ---- h' = (x @ W) * dis[row] ----
// EXACT R10 version (proven 370us total). 128 rows/block, 256 threads.
// Thread (r, c) computes rows r and r+64, cols {4j+c}. Per k: 2 xs LDS + 16 ws
// LDS reused across BOTH rows -> 32 FMA. Rotated xs rows keep banks conflict-free.
__global__ void k_gemm(const float* __restrict__ x, const float* __restrict__ W, int n) {
    __shared__ float xs[128 * 64];   // 32KB, rotated rows
    __shared__ float ws[64 * 64];    // 16KB -> total 48KB = limit
    int t = threadIdx.x;
    int R0 = blockIdx.x * 128;
    int rows = min(128, n - R0);

    for (int i = t; i < 64 * 16; i += 256)
        ((float4*)ws)[i] = ((const float4*)W)[i];
    for (int i = t; i < rows * 16; i += 256) {
        int rr = i >> 4, c4 = i & 15;
        int roff = ((c4 * 4 + rr * 4) & 63);          // rotated, 16B-aligned
        *(float4*)(xs + rr * 64 + roff) = *((const float4*)(x + (size_t)(R0 + rr) * 64) + c4);
    }
    __syncthreads();

    int r = t >> 2;      // 0..63 -> rows r and r+64
    int c = t & 3;       // 0..3  -> cols 4j+c
    bool v0 = (r < rows);
    bool v1 = (r + 64 < rows);
    if (!v0) return;

    const float* xrow0 = xs + r * 64;
    const float* xrow1 = xs + (r + 64) * 64;
    int rot = (r * 4) & 63;                           // same for r and r+64

    float acc0[16], acc1[16];
#pragma unroll
    for (int j = 0; j < 16; j++) { acc0[j] = 0.0f; acc1[j] = 0.0f; }
#pragma unroll
    for (int k = 0; k < 64; k++) {
        int koff = (k + rot) & 63;
        float xv0 = xrow0[koff];
        float xv1 = xrow1[koff];
        const float* wrow = ws + k * 64;
#pragma unroll
        for (int j = 0; j < 16; j++) {
            float w = wrow[4 * j + c];
            acc0[j] += xv0 * w;
            acc1[j] += xv1 * w;
        }
    }
    int gr0 = R0 + r;
    float s0 = g_dis[gr0];
    float* hp0 = g_h + (size_t)gr0 * 64;
#pragma unroll
    for (int j = 0; j < 16; j++) hp0[4 * j + c] = acc0[j] * s0;
    if (v1) {
        int gr1 = gr0 + 64;
        float s1 = g_dis[gr1];
        float* hp1 = g_h + (size_t)gr1 * 64;
#pragma unroll
        for (int j = 0; j < 16; j++) hp1[4 * j + c] = acc1[j] * s1;
    }
}

// ---- fused gather + epilogue + pooling ----
// 16 nodes/block x 16 threads/node (one float4 lane each). R10 structure;
// ONLY change: edge loop unrolled 4-deep (was 2) for double the MLP.
__global__ void k_gather(const float* __restrict__ b, const int* __restrict__ batch,
                         float* __restrict__ xout, int n) {
    int t = threadIdx.x;
    int ln = t & 15;          // float4 lane (cols 4*ln .. 4*ln+3)
    int nr = t >> 4;          // node-in-block 0..15
    int node = blockIdx.x * 16 + nr;

    float4 acc = {0.f, 0.f, 0.f, 0.f};
    float4 out = {0.f, 0.f, 0.f, 0.f};
    if (node < n) {
        acc = g_h4[(size_t)node * 16 + ln];           // self loop (already *dis[node])
        float4 accB = {0.f, 0.f, 0.f, 0.f};
        int st = g_start[node];
        int end = st + g_degE[node];
        int k = st;
        for (; k + 3 < end; k += 4) {
            int s0 = g_csr[k],     s1 = g_csr[k + 1];
            int s2 = g_csr[k + 2], s3 = g_csr[k + 3];
            float4 v0 = g_h4[(size_t)s0 * 16 + ln];
            float4 v1 = g_h4[(size_t)s1 * 16 + ln];
            float4 v2 = g_h4[(size_t)s2 * 16 + ln];
            float4 v3 = g_h4[(size_t)s3 * 16 + ln];
            acc.x += v0.x + v1.x;  accB.x += v2.x + v3.x;
            acc.y += v0.y + v1.y;  accB.y += v2.y + v3.y;
            acc.z += v0.z + v1.z;  accB.z += v2.z + v3.z;
            acc.w += v0.w + v1.w;  accB.w += v2.w + v3.w;
        }
        for (; k < end; k++) {
            int s0 = g_csr[k];
            float4 v0 = g_h4[(size_t)s0 * 16 + ln];
            acc.x += v0.x; acc.y += v0.y; acc.z += v0.z; acc.w += v0.w;
        }
        acc.x += accB.x; acc.y += accB.y; acc.z += accB.z; acc.w += accB.w;

        float d = g_dis[node];
        float4 bb = ((const float4*)b)[ln];
        out.x = fmaxf(fmaf(d, acc.x, bb.x), 0.f);
        out.y = fmaxf(fmaf(d, acc.y, bb.y), 0.f);
        out.z = fmaxf(fmaf(d, acc.z, bb.z), 0.f);
        out.w = fmaxf(fmaf(d, acc.w, bb.w), 0.f);
        ((float4*)xout)[(size_t)node * 16 + ln] = out;
    }

    // pooling
    int R0 = blockIdx.x * 16;
    int last = min(R0 + 15, n - 1);
    int gfirst = batch[R0];
    int glast = batch[last];

    if (gfirst == glast) {
        __shared__ float4 ssum[16][16];
        __shared__ float4 smax[16][16];
        ssum[nr][ln] = out;               // out==0 for node>=n: identity for sum, safe for relu-max
        smax[nr][ln] = out;
        __syncthreads();
#pragma unroll
        for (int off = 8; off > 0; off >>= 1) {
            if (nr < off) {
                float4 a = ssum[nr][ln], c2 = ssum[nr + off][ln];
                a.x += c2.x; a.y += c2.y; a.z += c2.z; a.w += c2.w;
                ssum[nr][ln] = a;
                float4 m = smax[nr][ln], c3 = smax[nr + off][ln];
                m.x = fmaxf(m.x, c3.x); m.y = fmaxf(m.y, c3.y);
                m.z = fmaxf(m.z, c3.z); m.w = fmaxf(m.w, c3.w);
                smax[nr][ln] = m;
            }
            __syncthreads();
        }
        if (nr == 0) {
            float4 s = ssum[0][ln];
            float4 m = smax[0][ln];
            float* gs = &g_gsum[gfirst * 64 + ln * 4];
            unsigned int* gm = (unsigned int*)&g_gmax[gfirst * 64 + ln * 4];
            atomicAdd(gs + 0, s.x); atomicAdd(gs + 1, s.y);
            atomicAdd(gs + 2, s.z); atomicAdd(gs + 3, s.w);
            atomicMax(gm + 0, __float_as_uint(m.x));
            atomicMax(gm + 1, __float_as_uint(m.y));
            atomicMax(gm + 2, __float_as_uint(m.z));
            atomicMax(gm + 3, __float_as_uint(m.w));
        }
    } else if (node < n) {
        int g = batch[node];
        float* gs = &g_gsum[g * 64 + ln * 4];
        unsigned int* gm = (unsigned int*)&g_gmax[g * 64 + ln * 4];
        atomicAdd(gs + 0, out.x); atomicAdd(gs + 1, out.y);
        atomicAdd(gs + 2, out.z); atomicAdd(gs + 3, out.w);
        atomicMax(gm + 0, __float_as_uint(out.x));
        atomicMax(gm + 1, __float_as_uint(out.y));
        atomicMax(gm + 2, __float_as_uint(out.z));
        atomicMax(gm + 3, __float_as_uint(out.w));
    }
}

// ---- accumulate per-layer pooled features into graph output; reset pool buffers ----
__global__ void k_graphacc(float* __restrict__ out_graph) {
    int i = blockIdx.x * blockDim.x + threadIdx.x;
    if (i >= GMAX * 64) return;
    int g = i >> 6, j = i & 63;
    out_graph[g * 128 + j] += g_gmax[i];
    out_graph[g * 128 + 64 + j] += g_gsum[i] / g_cnt[g];
    g_gmax[i] = 0.0f;
    g_gsum[i] = 0.0f;
}

extern "C" void kernel_launch(void* const* d_in, const int* in_sizes, int n_in,
                              void* d_out, int out_size) {
    const float* x = (const float*)d_in[0];
    const int* ei = (const int*)d_in[1];
    const int* batch = (const int*)d_in[2];
    const float* Ws[3] = {(const float*)d_in[3], (const float*)d_in[5], (const float*)d_in[7]};
    const float* bs[3] = {(const float*)d_in[4], (const float*)d_in[6], (const float*)d_in[8]};

    int n = in_sizes[2];
    int e = in_sizes[1] / 2;

    float* out = (float*)d_out;
    float* out_nodes = out;
    float* out_graph = out + (size_t)n * 64;

    float *buf0, *buf1;
    cudaGetSymbolAddress((void**)&buf0, g_buf04);
    cudaGetSymbolAddress((void**)&buf1, g_buf14);

    int nb = (n + 511) / 512;   // scan blocks (<=256)

    k_init<<<(n + 255) / 256, 256>>>(out_graph, n);
    k_deg<<<(e + 255) / 256, 256>>>(ei, e);
    k_dis<<<(n + 255) / 256, 256>>>(batch, n);
    k_scan1<<<nb, 512>>>(n);
    k_scan2<<<1, 256>>>(nb);
    k_scan3<<<(n + 255) / 256, 256>>>(n);
    k_fill<<<(e + 255) / 256, 256>>>(ei, e);

    const float* xin = x;
    float* xouts[3] = {buf0, buf1, out_nodes};
    for (int l = 0; l < 3; l++) {
        k_gemm<<<(n + 127) / 128, 256>>>(xin, Ws[l], n);
        k_gather<<<(n + 15) / 16, 256>>>(bs[l], batch, xouts[l], n);
        k_graphacc<<<16, 256>>>(out_graph);
        xin = xouts[l];
    }
}

// round 13
// speedup vs baseline: 1.2571x; 1.0407x over previous
#include <cuda_runtime.h>

#define D 64
#define GMAX 64
#define NMAX 100000
#define EMAX 1250000

// ---- scratch (device globals). float4 => 16B alignment. ----
__device__ float4 g_h4[NMAX * D / 4];     // h' = (x @ W) * dis[row]
__device__ float4 g_buf04[NMAX * D / 4];  // layer ping-pong
__device__ float4 g_buf14[NMAX * D / 4];
__device__ int   g_degE[NMAX];            // real in-degree (no self loop)
__device__ int   g_start[NMAX];           // CSR exclusive offsets
__device__ int   g_cursor[NMAX];          // fill cursors
__device__ int   g_csr[EMAX];             // src ids grouped by dst
__device__ int   g_bsum[256];             // scan block sums
__device__ int   g_boff[256];             // scan block offsets
__device__ float g_dis[NMAX];
__device__ float g_cnt[GMAX];
__device__ float g_gmax[GMAX * D];
__device__ float g_gsum[GMAX * D];

#define g_h ((float*)g_h4)

// ---- init ----
__global__ void k_init(float* __restrict__ out_graph, int n) {
    int i = blockIdx.x * blockDim.x + threadIdx.x;
    if (i < n) g_degE[i] = 0;
    if (i < GMAX) g_cnt[i] = 0.0f;
    if (i < GMAX * D) { g_gmax[i] = 0.0f; g_gsum[i] = 0.0f; }
    if (i < GMAX * 2 * D) out_graph[i] = 0.0f;
}

// ---- in-degree over destinations (int) ----
__global__ void k_deg(const int* __restrict__ ei, int e) {
    int i = blockIdx.x * blockDim.x + threadIdx.x;
    if (i < e) atomicAdd(&g_degE[ei[e + i]], 1);
}

// ---- dis = rsqrt(degE + 1); per-graph node counts ----
__global__ void k_dis(const int* __restrict__ batch, int n) {
    int i = blockIdx.x * blockDim.x + threadIdx.x;
    if (i < n) {
        g_dis[i] = rsqrtf((float)(g_degE[i] + 1));
        atomicAdd(&g_cnt[batch[i]], 1.0f);
    }
}

// ---- deterministic 2-level exclusive scan of g_degE -> g_start ----
__global__ void k_scan1(int n) {
    __shared__ int s[512];
    int i = blockIdx.x * 512 + threadIdx.x;
    int v = (i < n) ? g_degE[i] : 0;
    s[threadIdx.x] = v;
    __syncthreads();
    for (int off = 1; off < 512; off <<= 1) {
        int t = (threadIdx.x >= off) ? s[threadIdx.x - off] : 0;
        __syncthreads();
        s[threadIdx.x] += t;
        __syncthreads();
    }
    if (i < n) g_start[i] = s[threadIdx.x] - v;   // exclusive
    if (threadIdx.x == 511) g_bsum[blockIdx.x] = s[511];
}
__global__ void k_scan2(int nb) {
    __shared__ int s[256];
    int v = (threadIdx.x < nb) ? g_bsum[threadIdx.x] : 0;
    s[threadIdx.x] = v;
    __syncthreads();
    for (int off = 1; off < 256; off <<= 1) {
        int t = (threadIdx.x >= off) ? s[threadIdx.x - off] : 0;
        __syncthreads();
        s[threadIdx.x] += t;
        __syncthreads();
    }
    if (threadIdx.x < nb) g_boff[threadIdx.x] = s[threadIdx.x] - v;
}
__global__ void k_scan3(int n) {
    int i = blockIdx.x * blockDim.x + threadIdx.x;
    if (i < n) {
        int st = g_start[i] + g_boff[i >> 9];
        g_start[i] = st;
        g_cursor[i] = st;
    }
}

// ---- CSR fill: group src by dst (order within node nondeterministic; sum-safe) ----
__global__ void k_fill(const int* __restrict__ ei, int e) {
    int i = blockIdx.x * blockDim.x + threadIdx.x;
    if (i >= e) return;
    int dst = ei[e + i];
    int pos = atomicAdd(&g_cursor[dst], 1);
    g_csr[pos] = ei[i];
}

// ---- h' = (x @ W) * dis[row] ----
// 128 rows/block, 128 threads (R11's GEMM, now tested in isolation).
// Thread (r, c) computes rows r, r+32, r+64, r+96, cols {4j+c}. Per k:
// 4 xs LDS + 16 ws LDS reused across 4 rows -> 64 FMA (LDS/FMA 0.31).
// Rotation (4*row)&63 identical for all 4 rows; ws pattern = proven kernel.
__global__ void k_gemm(const float* __restrict__ x, const float* __restrict__ W, int n) {
    __shared__ float xs[128 * 64];   // 32KB, rotated rows
    __shared__ float ws[64 * 64];    // 16KB -> total 48KB = limit
    int t = threadIdx.x;             // 0..127
    int R0 = blockIdx.x * 128;
    int rows = min(128, n - R0);

    for (int i = t; i < 64 * 16; i += 128)
        ((float4*)ws)[i] = ((const float4*)W)[i];
    for (int i = t; i < rows * 16; i += 128) {
        int rr = i >> 4, c4 = i & 15;
        int roff = ((c4 * 4 + rr * 4) & 63);          // rotated, 16B-aligned
        *(float4*)(xs + rr * 64 + roff) = *((const float4*)(x + (size_t)(R0 + rr) * 64) + c4);
    }
    __syncthreads();

    int r = t >> 2;      // 0..31 -> rows r, r+32, r+64, r+96
    int c = t & 3;       // 0..3  -> cols 4j+c
    int rot = (r * 4) & 63;
    const float* x0 = xs + r * 64;
    const float* x1 = xs + (r + 32) * 64;
    const float* x2 = xs + (r + 64) * 64;
    const float* x3 = xs + (r + 96) * 64;

    float acc0[16], acc1[16], acc2[16], acc3[16];
#pragma unroll
    for (int j = 0; j < 16; j++) { acc0[j] = 0.f; acc1[j] = 0.f; acc2[j] = 0.f; acc3[j] = 0.f; }
#pragma unroll 16
    for (int k = 0; k < 64; k++) {
        int koff = (k + rot) & 63;
        float xv0 = x0[koff];
        float xv1 = x1[koff];
        float xv2 = x2[koff];
        float xv3 = x3[koff];
        const float* wrow = ws + k * 64;
#pragma unroll
        for (int j = 0; j < 16; j++) {
            float w = wrow[4 * j + c];
            acc0[j] += xv0 * w;
            acc1[j] += xv1 * w;
            acc2[j] += xv2 * w;
            acc3[j] += xv3 * w;
        }
    }
#pragma unroll
    for (int q = 0; q < 4; q++) {
        int gr = R0 + r + q * 32;
        if (r + q * 32 < rows) {
            float s = g_dis[gr];
            float* hp = g_h + (size_t)gr * 64;
            const float* a = (q == 0) ? acc0 : (q == 1) ? acc1 : (q == 2) ? acc2 : acc3;
#pragma unroll
            for (int j = 0; j < 16; j++) hp[4 * j + c] = a[j] * s;
        }
    }
}

// ---- fused gather + epilogue + pooling ----
// EXACT R12 version (370-373us proven). 16 nodes/block x 16 threads/node.
__global__ void k_gather(const float* __restrict__ b, const int* __restrict__ batch,
                         float* __restrict__ xout, int n) {
    int t = threadIdx.x;
    int ln = t & 15;          // float4 lane (cols 4*ln .. 4*ln+3)
    int nr = t >> 4;          // node-in-block 0..15
    int node = blockIdx.x * 16 + nr;

    float4 acc = {0.f, 0.f, 0.f, 0.f};
    float4 out = {0.f, 0.f, 0.f, 0.f};
    if (node < n) {
        acc = g_h4[(size_t)node * 16 + ln];           // self loop (already *dis[node])
        float4 accB = {0.f, 0.f, 0.f, 0.f};
        int st = g_start[node];
        int end = st + g_degE[node];
        int k = st;
        for (; k + 3 < end; k += 4) {
            int s0 = g_csr[k],     s1 = g_csr[k + 1];
            int s2 = g_csr[k + 2], s3 = g_csr[k + 3];
            float4 v0 = g_h4[(size_t)s0 * 16 + ln];
            float4 v1 = g_h4[(size_t)s1 * 16 + ln];
            float4 v2 = g_h4[(size_t)s2 * 16 + ln];
            float4 v3 = g_h4[(size_t)s3 * 16 + ln];
            acc.x += v0.x + v1.x;  accB.x += v2.x + v3.x;
            acc.y += v0.y + v1.y;  accB.y += v2.y + v3.y;
            acc.z += v0.z + v1.z;  accB.z += v2.z + v3.z;
            acc.w += v0.w + v1.w;  accB.w += v2.w + v3.w;
        }
        for (; k < end; k++) {
            int s0 = g_csr[k];
            float4 v0 = g_h4[(size_t)s0 * 16 + ln];
            acc.x += v0.x; acc.y += v0.y; acc.z += v0.z; acc.w += v0.w;
        }
        acc.x += accB.x; acc.y += accB.y; acc.z += accB.z; acc.w += accB.w;

        float d = g_dis[node];
        float4 bb = ((const float4*)b)[ln];
        out.x = fmaxf(fmaf(d, acc.x, bb.x), 0.f);
        out.y = fmaxf(fmaf(d, acc.y, bb.y), 0.f);
        out.z = fmaxf(fmaf(d, acc.z, bb.z), 0.f);
        out.w = fmaxf(fmaf(d, acc.w, bb.w), 0.f);
        ((float4*)xout)[(size_t)node * 16 + ln] = out;
    }

    // pooling
    int R0 = blockIdx.x * 16;
    int last = min(R0 + 15, n - 1);
    int gfirst = batch[R0];
    int glast = batch[last];

    if (gfirst == glast) {
        __shared__ float4 ssum[16][16];
        __shared__ float4 smax[16][16];
        ssum[nr][ln] = out;               // out==0 for node>=n: identity for sum, safe for relu-max
        smax[nr][ln] = out;
        __syncthreads();
#pragma unroll
        for (int off = 8; off > 0; off >>= 1) {
            if (nr < off) {
                float4 a = ssum[nr][ln], c2 = ssum[nr + off][ln];
                a.x += c2.x; a.y += c2.y; a.z += c2.z; a.w += c2.w;
                ssum[nr][ln] = a;
                float4 m = smax[nr][ln], c3 = smax[nr + off][ln];
                m.x = fmaxf(m.x, c3.x); m.y = fmaxf(m.y, c3.y);
                m.z = fmaxf(m.z, c3.z); m.w = fmaxf(m.w, c3.w);
                smax[nr][ln] = m;
            }
            __syncthreads();
        }
        if (nr == 0) {
            float4 s = ssum[0][ln];
            float4 m = smax[0][ln];
            float* gs = &g_gsum[gfirst * 64 + ln * 4];
            unsigned int* gm = (unsigned int*)&g_gmax[gfirst * 64 + ln * 4];
            atomicAdd(gs + 0, s.x); atomicAdd(gs + 1, s.y);
            atomicAdd(gs + 2, s.z); atomicAdd(gs + 3, s.w);
            atomicMax(gm + 0, __float_as_uint(m.x));
            atomicMax(gm + 1, __float_as_uint(m.y));
            atomicMax(gm + 2, __float_as_uint(m.z));
            atomicMax(gm + 3, __float_as_uint(m.w));
        }
    } else if (node < n) {
        int g = batch[node];
        float* gs = &g_gsum[g * 64 + ln * 4];
        unsigned int* gm = (unsigned int*)&g_gmax[g * 64 + ln * 4];
        atomicAdd(gs + 0, out.x); atomicAdd(gs + 1, out.y);
        atomicAdd(gs + 2, out.z); atomicAdd(gs + 3, out.w);
        atomicMax(gm + 0, __float_as_uint(out.x));
        atomicMax(gm + 1, __float_as_uint(out.y));
        atomicMax(gm + 2, __float_as_uint(out.z));
        atomicMax(gm + 3, __float_as_uint(out.w));
    }
}

// ---- accumulate per-layer pooled features into graph output; reset pool buffers ----
__global__ void k_graphacc(float* __restrict__ out_graph) {
    int i = blockIdx.x * blockDim.x + threadIdx.x;
    if (i >= GMAX * 64) return;
    int g = i >> 6, j = i & 63;
    out_graph[g * 128 + j] += g_gmax[i];
    out_graph[g * 128 + 64 + j] += g_gsum[i] / g_cnt[g];
    g_gmax[i] = 0.0f;
    g_gsum[i] = 0.0f;
}

extern "C" void kernel_launch(void* const* d_in, const int* in_sizes, int n_in,
                              void* d_out, int out_size) {
    const float* x = (const float*)d_in[0];
    const int* ei = (const int*)d_in[1];
    const int* batch = (const int*)d_in[2];
    const float* Ws[3] = {(const float*)d_in[3], (const float*)d_in[5], (const float*)d_in[7]};
    const float* bs[3] = {(const float*)d_in[4], (const float*)d_in[6], (const float*)d_in[8]};

    int n = in_sizes[2];
    int e = in_sizes[1] / 2;

    float* out = (float*)d_out;
    float* out_nodes = out;
    float* out_graph = out + (size_t)n * 64;

    float *buf0, *buf1;
    cudaGetSymbolAddress((void**)&buf0, g_buf04);
    cudaGetSymbolAddress((void**)&buf1, g_buf14);

    int nb = (n + 511) / 512;   // scan blocks (<=256)

    k_init<<<(n + 255) / 256, 256>>>(out_graph, n);
    k_deg<<<(e + 255) / 256, 256>>>(ei, e);
    k_dis<<<(n + 255) / 256, 256>>>(batch, n);
    k_scan1<<<nb, 512>>>(n);
    k_scan2<<<1, 256>>>(nb);
    k_scan3<<<(n + 255) / 256, 256>>>(n);
    k_fill<<<(e + 255) / 256, 256>>>(ei, e);

    const float* xin = x;
    float* xouts[3] = {buf0, buf1, out_nodes};
    for (int l = 0; l < 3; l++) {
        k_gemm<<<(n + 127) / 128, 128>>>(xin, Ws[l], n);
        k_gather<<<(n + 15) / 16, 256>>>(bs[l], batch, xouts[l], n);
        k_graphacc<<<16, 256>>>(out_graph);
        xin = xouts[l];
    }
}